// round 11
// baseline (speedup 1.0000x reference)
#include <cuda_runtime.h>
#include <cstdint>

// Problem constants: x is (16384, 2048) fp32, angles (2048,) fp32, out (16384, 2048) fp32.
constexpr int NN = 2048;   // row length n
constexpr int T  = 256;    // threads per block
constexpr int E  = 8;      // elements per thread (T*E == NN)
constexpr int R  = 6;      // rows per block (processed as 2 triplets)

// y_row = G_0 (G_1 (... (G_{N-1} x_row))). First-order affine recurrence on the
// carry; Q-only weighted warp suffix scan. All row-independent constants
// (sin/cos, P-side scan weights) derived inline per block via log-depth shuffle
// scans — no prep kernel. THREE rows per iteration: three independent scan
// chains interleave (hiding SHFL latency), 6 LDG.128 in flight per warp, and
// one barrier serves three rows.
__global__ void __launch_bounds__(T, 3) givens_kernel(const float* __restrict__ x,
                                                      const float* __restrict__ ang,
                                                      float* __restrict__ y,
                                                      int rows) {
    __shared__ __align__(16) float wtQ[2][3][8];  // [triplet parity][row][warp]
    __shared__ float sxe[2][3][8];                // lane-31 x[lo+7] per warp
    __shared__ float sx01[2][3][2];               // x[0], x[N-1]
    __shared__ float spw[8];                      // per-warp P totals
    __shared__ float scs[8][2];                   // per-warp tail coefficients (c,s at lo+7, lane 31)
    __shared__ float stail[2];                    // cN, sN (coefficients at N-1)

    const int t   = threadIdx.x;
    const int lid = t & 31;
    const int w   = t >> 5;
    const int lo  = t * E;
    const long base = (long)blockIdx.x * R;
    if (base >= rows) return;

    // ================= inline prep (row-independent) =================
    float cc[E], ss[E];
    {
        float4 a0 = reinterpret_cast<const float4*>(ang + lo)[0];
        float4 a1 = reinterpret_cast<const float4*>(ang + lo)[1];
        __sincosf(a0.x, &ss[0], &cc[0]);
        __sincosf(a0.y, &ss[1], &cc[1]);
        __sincosf(a0.z, &ss[2], &cc[2]);
        __sincosf(a0.w, &ss[3], &cc[3]);
        __sincosf(a1.x, &ss[4], &cc[4]);
        __sincosf(a1.y, &ss[5], &cc[5]);
        __sincosf(a1.z, &ss[6], &cc[6]);
        __sincosf(a1.w, &ss[7], &cc[7]);
    }

    // Per-thread P = prod of (-s_k) over this chunk (k = N-1 is the seed, skipped).
    float P = 1.f;
#pragma unroll
    for (int m = E - 1; m >= 0; --m) {
        if (lo + m == NN - 1) continue;
        P *= -ss[m];
    }

    // Warp suffix-scan jump weights by shuffle product-doubling:
    // W[di] = prod_{i < 2^di} P_{lid+i}  (0 past warp end).
    float W[5];
    {
        float S = P;
        W[0] = (lid + 1 < 32) ? S : 0.f;
#pragma unroll
        for (int di = 1; di < 5; ++di) {
            const int h = 1 << (di - 1);
            float Sn = __shfl_down_sync(0xffffffffu, S, h);
            S *= (lid + h < 32) ? Sn : 0.f;
            W[di] = (lid + (1 << di) < 32) ? S : 0.f;
        }
    }

    // Warp inclusive suffix scan of P -> Pe (exclusive), warp totals.
    float Pscan = P;
#pragma unroll
    for (int d = 1; d < 32; d <<= 1) {
        float tmp = __shfl_down_sync(0xffffffffu, Pscan, d);
        if (lid + d < 32) Pscan *= tmp;
    }
    float Pe = __shfl_down_sync(0xffffffffu, Pscan, 1);
    if (lid == 31) Pe = 1.f;

    if (lid == 0)  spw[w] = Pscan;
    if (lid == 31) { scs[w][0] = cc[7]; scs[w][1] = ss[7]; }
    if (t == T - 1) { stail[0] = cc[7]; stail[1] = ss[7]; }
    __syncthreads();                                     // one barrier for all of prep

    float Pf = Pe;
    for (int w2 = w + 1; w2 < 8; ++w2) Pf *= spw[w2];    // block-exclusive product
    const float pw1 = spw[1], pw2 = spw[2], pw3 = spw[3],
                pw4 = spw[4], pw5 = spw[5], pw6 = spw[6];
    const float cN = stail[0];
    const float sN = stail[1];

    // Warp-head lanes (lane 0 of warps 1..7) rebuild out[lo] locally:
    // out[lo] = s[lo-1]*x[lo-1] + c[lo-1]*prev_lo.
    const bool warp_head = (lid == 0) && (w > 0);
    float cprev = 0.f, sprev = 0.f;
    if (warp_head) { cprev = scs[w - 1][0]; sprev = scs[w - 1][1]; }

    // ================= main loop: three rows per iteration =================
#pragma unroll 1
    for (int r = 0; r < R; r += 3) {
        if (base + r >= rows) break;
        const bool hasB = (base + r + 1 < rows);
        const bool hasC = (base + r + 2 < rows);
        const int buf = (r / 3) & 1;
        const float* xrA = x + (base + r) * NN;
        const float* xrB = hasB ? (x + (base + r + 1) * NN) : xrA;
        const float* xrC = hasC ? (x + (base + r + 2) * NN) : xrA;

        // ---- loads for all three rows (6 LDG.128 in flight) ----
        float xa[E], xb[E], xc[E];
        {
            float4 a0 = __ldcs(reinterpret_cast<const float4*>(xrA + lo));
            float4 a1 = __ldcs(reinterpret_cast<const float4*>(xrA + lo) + 1);
            float4 b0 = __ldcs(reinterpret_cast<const float4*>(xrB + lo));
            float4 b1 = __ldcs(reinterpret_cast<const float4*>(xrB + lo) + 1);
            float4 c0 = __ldcs(reinterpret_cast<const float4*>(xrC + lo));
            float4 c1 = __ldcs(reinterpret_cast<const float4*>(xrC + lo) + 1);
            xa[0] = a0.x; xa[1] = a0.y; xa[2] = a0.z; xa[3] = a0.w;
            xa[4] = a1.x; xa[5] = a1.y; xa[6] = a1.z; xa[7] = a1.w;
            xb[0] = b0.x; xb[1] = b0.y; xb[2] = b0.z; xb[3] = b0.w;
            xb[4] = b1.x; xb[5] = b1.y; xb[6] = b1.z; xb[7] = b1.w;
            xc[0] = c0.x; xc[1] = c0.y; xc[2] = c0.z; xc[3] = c0.w;
            xc[4] = c1.x; xc[5] = c1.y; xc[6] = c1.z; xc[7] = c1.w;
        }
        // Boundary exchange through smem (pre-barrier writes):
        if (lid == 31) {
            sxe[buf][0][w] = xa[7]; sxe[buf][1][w] = xb[7]; sxe[buf][2][w] = xc[7];
        }
        if (t == 0) {
            sx01[buf][0][0] = xa[0]; sx01[buf][1][0] = xb[0]; sx01[buf][2][0] = xc[0];
        }
        if (t == T-1) {
            sx01[buf][0][1] = xa[7]; sx01[buf][1][1] = xb[7]; sx01[buf][2][1] = xc[7];
        }

        // ---- Q composition, three independent chains ----
        // Thread 0's Q uses the UNcorrected x[0]; that Q is consumed by nobody.
        float QA = 0.f, QB = 0.f, QC = 0.f;
#pragma unroll
        for (int m = E - 1; m >= 0; --m) {
            if (lo + m == NN - 1) continue;            // seed step
            QA = fmaf(-ss[m], QA, cc[m] * xa[m]);
            QB = fmaf(-ss[m], QB, cc[m] * xb[m]);
            QC = fmaf(-ss[m], QC, cc[m] * xc[m]);
        }

        // ---- Q-only weighted warp suffix scan, three rows interleaved ----
#pragma unroll
        for (int di = 0, d = 1; di < 5; ++di, d <<= 1) {
            float qa2 = __shfl_down_sync(0xffffffffu, QA, d);
            float qb2 = __shfl_down_sync(0xffffffffu, QB, d);
            float qc2 = __shfl_down_sync(0xffffffffu, QC, d);
            QA = fmaf(W[di], qa2, QA);
            QB = fmaf(W[di], qb2, QB);
            QC = fmaf(W[di], qc2, QC);
        }
        float QeA = __shfl_down_sync(0xffffffffu, QA, 1);
        float QeB = __shfl_down_sync(0xffffffffu, QB, 1);
        float QeC = __shfl_down_sync(0xffffffffu, QC, 1);
        if (lid == 31) { QeA = 0.f; QeB = 0.f; QeC = 0.f; }

        if (lid == 0) {
            wtQ[buf][0][w] = QA; wtQ[buf][1][w] = QB; wtQ[buf][2][w] = QC;
        }
        __syncthreads();                                // ONE barrier for three rows

        // ---- cross-warp Horner over later warps, three rows ----
        float4 qa0 = *reinterpret_cast<const float4*>(&wtQ[buf][0][0]);
        float4 qa1 = *reinterpret_cast<const float4*>(&wtQ[buf][0][4]);
        float4 qb0 = *reinterpret_cast<const float4*>(&wtQ[buf][1][0]);
        float4 qb1 = *reinterpret_cast<const float4*>(&wtQ[buf][1][4]);
        float4 qc0 = *reinterpret_cast<const float4*>(&wtQ[buf][2][0]);
        float4 qc1 = *reinterpret_cast<const float4*>(&wtQ[buf][2][4]);
        float QpA = 0.f, QpB = 0.f, QpC = 0.f;
        if (w < 7) { QpA = qa1.w;                 QpB = qb1.w;                 QpC = qc1.w; }
        if (w < 6) { QpA = fmaf(pw6, QpA, qa1.z); QpB = fmaf(pw6, QpB, qb1.z); QpC = fmaf(pw6, QpC, qc1.z); }
        if (w < 5) { QpA = fmaf(pw5, QpA, qa1.y); QpB = fmaf(pw5, QpB, qb1.y); QpC = fmaf(pw5, QpC, qc1.y); }
        if (w < 4) { QpA = fmaf(pw4, QpA, qa1.x); QpB = fmaf(pw4, QpB, qb1.x); QpC = fmaf(pw4, QpC, qc1.x); }
        if (w < 3) { QpA = fmaf(pw3, QpA, qa0.w); QpB = fmaf(pw3, QpB, qb0.w); QpC = fmaf(pw3, QpC, qc0.w); }
        if (w < 2) { QpA = fmaf(pw2, QpA, qa0.z); QpB = fmaf(pw2, QpB, qb0.z); QpC = fmaf(pw2, QpC, qc0.z); }
        if (w < 1) { QpA = fmaf(pw1, QpA, qa0.y); QpB = fmaf(pw1, QpB, qb0.y); QpC = fmaf(pw1, QpC, qc0.y); }

        const float x0A = sx01[buf][0][0], xn1A = sx01[buf][0][1];
        const float x0B = sx01[buf][1][0], xn1B = sx01[buf][1][1];
        const float x0C = sx01[buf][2][0], xn1C = sx01[buf][2][1];
        const float seedA = fmaf(cN, xn1A, -sN * x0A);  // prev_{N-1}
        const float seedB = fmaf(cN, xn1B, -sN * x0B);
        const float seedC = fmaf(cN, xn1C, -sN * x0C);
        if (t == 0) {
            xa[0] = fmaf(sN, xn1A, cN * x0A);           // X_0 fix before replay
            xb[0] = fmaf(sN, xn1B, cN * x0B);
            xc[0] = fmaf(sN, xn1C, cN * x0C);
        }

        float prevA = fmaf(Pf, seedA, fmaf(Pe, QpA, QeA));
        float prevB = fmaf(Pf, seedB, fmaf(Pe, QpB, QeB));
        float prevC = fmaf(Pf, seedC, fmaf(Pe, QpC, QeC));

        // ---- replay in place, three rows; ends with prev = prev_lo ----
#pragma unroll
        for (int m = E - 1; m >= 0; --m) {
            if (lo + m == NN - 1) { xa[m] = 0.f; xb[m] = 0.f; xc[m] = 0.f; continue; }
            const float xmA = xa[m], xmB = xb[m], xmC = xc[m];
            xa[m] = fmaf(ss[m], xmA, cc[m] * prevA);
            prevA = fmaf(-ss[m], prevA, cc[m] * xmA);
            xb[m] = fmaf(ss[m], xmB, cc[m] * prevB);
            prevB = fmaf(-ss[m], prevB, cc[m] * xmB);
            xc[m] = fmaf(ss[m], xmC, cc[m] * prevC);
            prevC = fmaf(-ss[m], prevC, cc[m] * xmC);
        }

        // out[lo]: lanes 1-31 take previous lane's xv[7]; warp heads recompute;
        // thread 0 has it as prev_0.
        float carryA = __shfl_up_sync(0xffffffffu, xa[E - 1], 1);
        float carryB = __shfl_up_sync(0xffffffffu, xb[E - 1], 1);
        float carryC = __shfl_up_sync(0xffffffffu, xc[E - 1], 1);
        if (t == 0) {
            carryA = prevA; carryB = prevB; carryC = prevC;
        } else if (warp_head) {
            carryA = fmaf(sprev, sxe[buf][0][w - 1], cprev * prevA);
            carryB = fmaf(sprev, sxe[buf][1][w - 1], cprev * prevB);
            carryC = fmaf(sprev, sxe[buf][2][w - 1], cprev * prevC);
        }

        float* yrA = y + (base + r) * NN;
        float4 oa0, oa1;
        oa0.x = carryA; oa0.y = xa[0]; oa0.z = xa[1]; oa0.w = xa[2];
        oa1.x = xa[3];  oa1.y = xa[4]; oa1.z = xa[5]; oa1.w = xa[6];
        __stcs(reinterpret_cast<float4*>(yrA + lo), oa0);
        __stcs(reinterpret_cast<float4*>(yrA + lo) + 1, oa1);
        if (hasB) {
            float* yrB = y + (base + r + 1) * NN;
            float4 ob0, ob1;
            ob0.x = carryB; ob0.y = xb[0]; ob0.z = xb[1]; ob0.w = xb[2];
            ob1.x = xb[3];  ob1.y = xb[4]; ob1.z = xb[5]; ob1.w = xb[6];
            __stcs(reinterpret_cast<float4*>(yrB + lo), ob0);
            __stcs(reinterpret_cast<float4*>(yrB + lo) + 1, ob1);
        }
        if (hasC) {
            float* yrC = y + (base + r + 2) * NN;
            float4 oc0, oc1;
            oc0.x = carryC; oc0.y = xc[0]; oc0.z = xc[1]; oc0.w = xc[2];
            oc1.x = xc[3];  oc1.y = xc[4]; oc1.z = xc[5]; oc1.w = xc[6];
            __stcs(reinterpret_cast<float4*>(yrC + lo), oc0);
            __stcs(reinterpret_cast<float4*>(yrC + lo) + 1, oc1);
        }
    }
}

extern "C" void kernel_launch(void* const* d_in, const int* in_sizes, int n_in,
                              void* d_out, int out_size) {
    const float* x   = (const float*)d_in[0];   // (B, N) fp32
    const float* ang = (const float*)d_in[1];   // (N,)  fp32
    float* y = (float*)d_out;                   // (B, N) fp32

    const int rows   = out_size / NN;           // B = 16384
    const int blocks = (rows + R - 1) / R;      // 2731
    givens_kernel<<<blocks, T>>>(x, ang, y, rows);
}

// round 12
// speedup vs baseline: 1.0396x; 1.0396x over previous
#include <cuda_runtime.h>
#include <cstdint>

// Problem constants: x is (16384, 2048) fp32, angles (2048,) fp32, out (16384, 2048) fp32.
constexpr int NN = 2048;   // row length n
constexpr int T  = 256;    // threads per block
constexpr int E  = 8;      // elements per thread (T*E == NN)
constexpr int R  = 4;      // rows per block, straight-line quad-load / dual-compute

// y_row = G_0 (G_1 (... (G_{N-1} x_row))). First-order affine recurrence on the
// carry; Q-only weighted warp suffix scan. Straight-line: ALL FOUR rows' loads
// issue first (DRAM latency overlaps the inline prep), then two dual-row
// compute phases. Row-independent constants (sin/cos coeffs, scan weights) live
// in conflict-free private smem, not registers, so the 4-row residency fits
// the 64-reg / 4-CTA budget.
__global__ void __launch_bounds__(T, 4) givens_kernel(const float* __restrict__ x,
                                                      const float* __restrict__ ang,
                                                      float* __restrict__ y,
                                                      int rows) {
    // Private per-thread coefficient slices; granule index == thread index ->
    // conflict-free LDS.128 (8 threads/phase span 32 distinct banks).
    __shared__ __align__(16) float4 sC0[T], sC1[T], sS0[T], sS1[T];
    __shared__ float sW[T][5];                    // stride 5 (coprime 32): conflict-free
    __shared__ __align__(16) float spw[8];        // per-warp P totals
    __shared__ float scs[8][2];                   // per-warp tail coeffs (c,s at lo+7, lane 31)
    __shared__ float stail[2];                    // cN, sN
    __shared__ __align__(16) float wtQ[2][2][8];  // [phase][row-in-pair][warp]
    __shared__ float sxe[4][8];                   // lane-31 x[lo+7] per warp, per row
    __shared__ float sx01[4][2];                  // x[0], x[N-1] per row

    const int t   = threadIdx.x;
    const int lid = t & 31;
    const int w   = t >> 5;
    const int lo  = t * E;
    const long base = (long)blockIdx.x * R;
    if (base >= rows) return;

    const bool hasB = base + 1 < rows;
    const bool hasC = base + 2 < rows;
    const bool hasD = base + 3 < rows;
    const float* xrA = x + base * NN;
    const float* xrB = xrA + (hasB ? NN : 0);
    const float* xrC = xrA + (hasC ? 2 * NN : 0);
    const float* xrD = xrA + (hasD ? 3 * NN : 0);

    // ================= 1. issue ALL row loads first =================
    float4 a0 = __ldcs(reinterpret_cast<const float4*>(xrA + lo));
    float4 a1 = __ldcs(reinterpret_cast<const float4*>(xrA + lo) + 1);
    float4 b0 = __ldcs(reinterpret_cast<const float4*>(xrB + lo));
    float4 b1 = __ldcs(reinterpret_cast<const float4*>(xrB + lo) + 1);
    float4 cv0 = __ldcs(reinterpret_cast<const float4*>(xrC + lo));
    float4 cv1 = __ldcs(reinterpret_cast<const float4*>(xrC + lo) + 1);
    float4 dv0 = __ldcs(reinterpret_cast<const float4*>(xrD + lo));
    float4 dv1 = __ldcs(reinterpret_cast<const float4*>(xrD + lo) + 1);

    // ================= 2. inline prep (overlaps DRAM latency) =================
    float Pe;
    {
        float4 g0 = reinterpret_cast<const float4*>(ang + lo)[0];
        float4 g1 = reinterpret_cast<const float4*>(ang + lo)[1];
        float cc[E], ss[E];
        __sincosf(g0.x, &ss[0], &cc[0]);
        __sincosf(g0.y, &ss[1], &cc[1]);
        __sincosf(g0.z, &ss[2], &cc[2]);
        __sincosf(g0.w, &ss[3], &cc[3]);
        __sincosf(g1.x, &ss[4], &cc[4]);
        __sincosf(g1.y, &ss[5], &cc[5]);
        __sincosf(g1.z, &ss[6], &cc[6]);
        __sincosf(g1.w, &ss[7], &cc[7]);
        sC0[t] = make_float4(cc[0], cc[1], cc[2], cc[3]);
        sC1[t] = make_float4(cc[4], cc[5], cc[6], cc[7]);
        sS0[t] = make_float4(ss[0], ss[1], ss[2], ss[3]);
        sS1[t] = make_float4(ss[4], ss[5], ss[6], ss[7]);

        // Per-thread P = prod of (-s_k) over this chunk (k = N-1 is the seed, skipped).
        float P = 1.f;
#pragma unroll
        for (int m = E - 1; m >= 0; --m) {
            if (lo + m == NN - 1) continue;
            P *= -ss[m];
        }

        // Warp suffix-scan jump weights by shuffle product-doubling (0 past warp end).
        {
            float S = P;
            sW[t][0] = (lid + 1 < 32) ? S : 0.f;
#pragma unroll
            for (int di = 1; di < 5; ++di) {
                const int h = 1 << (di - 1);
                float Sn = __shfl_down_sync(0xffffffffu, S, h);
                S *= (lid + h < 32) ? Sn : 0.f;
                sW[t][di] = (lid + (1 << di) < 32) ? S : 0.f;
            }
        }

        // Warp inclusive suffix scan of P -> Pe (exclusive), warp totals.
        float Pscan = P;
#pragma unroll
        for (int d = 1; d < 32; d <<= 1) {
            float tmp = __shfl_down_sync(0xffffffffu, Pscan, d);
            if (lid + d < 32) Pscan *= tmp;
        }
        Pe = __shfl_down_sync(0xffffffffu, Pscan, 1);
        if (lid == 31) Pe = 1.f;

        if (lid == 0)   spw[w] = Pscan;
        if (lid == 31)  { scs[w][0] = cc[7]; scs[w][1] = ss[7]; }
        if (t == T - 1) { stail[0] = cc[7]; stail[1] = ss[7]; }
    }

    // Boundary exchange for ALL FOUR rows (pre-barrier writes; loads have landed
    // for the few threads that need them by the time they execute this).
    if (lid == 31) {
        sxe[0][w] = a1.w; sxe[1][w] = b1.w; sxe[2][w] = cv1.w; sxe[3][w] = dv1.w;
    }
    if (t == 0) {
        sx01[0][0] = a0.x; sx01[1][0] = b0.x; sx01[2][0] = cv0.x; sx01[3][0] = dv0.x;
    }
    if (t == T - 1) {
        sx01[0][1] = a1.w; sx01[1][1] = b1.w; sx01[2][1] = cv1.w; sx01[3][1] = dv1.w;
    }
    __syncthreads();                               // barrier 0: tables + boundaries ready

    float Pf = Pe;
    for (int w2 = w + 1; w2 < 8; ++w2) Pf *= spw[w2];   // block-exclusive product
    const float cN = stail[0];
    const float sN = stail[1];
    const bool warp_head = (lid == 0) && (w > 0);
    float cprev = 0.f, sprev = 0.f;
    if (warp_head) { cprev = scs[w - 1][0]; sprev = scs[w - 1][1]; }

    // ======================= PHASE 1: rows A, B =======================
    {
        float xa[E], xb[E];
        xa[0] = a0.x; xa[1] = a0.y; xa[2] = a0.z; xa[3] = a0.w;
        xa[4] = a1.x; xa[5] = a1.y; xa[6] = a1.z; xa[7] = a1.w;
        xb[0] = b0.x; xb[1] = b0.y; xb[2] = b0.z; xb[3] = b0.w;
        xb[4] = b1.x; xb[5] = b1.y; xb[6] = b1.z; xb[7] = b1.w;

        // Q composition (coeffs from smem; thread 0's Q is consumed by nobody).
        float QA = 0.f, QB = 0.f;
        {
            float4 C0 = sC0[t], C1 = sC1[t], S0 = sS0[t], S1 = sS1[t];
            const float cc[E] = {C0.x, C0.y, C0.z, C0.w, C1.x, C1.y, C1.z, C1.w};
            const float ss[E] = {S0.x, S0.y, S0.z, S0.w, S1.x, S1.y, S1.z, S1.w};
#pragma unroll
            for (int m = E - 1; m >= 0; --m) {
                if (lo + m == NN - 1) continue;        // seed step
                QA = fmaf(-ss[m], QA, cc[m] * xa[m]);
                QB = fmaf(-ss[m], QB, cc[m] * xb[m]);
            }
        }

        // Q-only weighted warp suffix scan, rows interleaved; weights from smem.
#pragma unroll
        for (int di = 0, d = 1; di < 5; ++di, d <<= 1) {
            const float Wd = sW[t][di];
            float qa2 = __shfl_down_sync(0xffffffffu, QA, d);
            float qb2 = __shfl_down_sync(0xffffffffu, QB, d);
            QA = fmaf(Wd, qa2, QA);
            QB = fmaf(Wd, qb2, QB);
        }
        float QeA = __shfl_down_sync(0xffffffffu, QA, 1);
        float QeB = __shfl_down_sync(0xffffffffu, QB, 1);
        if (lid == 31) { QeA = 0.f; QeB = 0.f; }

        if (lid == 0) { wtQ[0][0][w] = QA; wtQ[0][1][w] = QB; }
        __syncthreads();                               // barrier 1

        // Cross-warp Horner over later warps (pw from smem).
        float4 qa0 = *reinterpret_cast<const float4*>(&wtQ[0][0][0]);
        float4 qa1 = *reinterpret_cast<const float4*>(&wtQ[0][0][4]);
        float4 qb0 = *reinterpret_cast<const float4*>(&wtQ[0][1][0]);
        float4 qb1 = *reinterpret_cast<const float4*>(&wtQ[0][1][4]);
        float4 pwa = *reinterpret_cast<const float4*>(&spw[0]);
        float4 pwb = *reinterpret_cast<const float4*>(&spw[4]);
        float QpA = 0.f, QpB = 0.f;
        if (w < 7) { QpA = qa1.w;                   QpB = qb1.w; }
        if (w < 6) { QpA = fmaf(pwb.z, QpA, qa1.z); QpB = fmaf(pwb.z, QpB, qb1.z); }
        if (w < 5) { QpA = fmaf(pwb.y, QpA, qa1.y); QpB = fmaf(pwb.y, QpB, qb1.y); }
        if (w < 4) { QpA = fmaf(pwb.x, QpA, qa1.x); QpB = fmaf(pwb.x, QpB, qb1.x); }
        if (w < 3) { QpA = fmaf(pwa.w, QpA, qa0.w); QpB = fmaf(pwa.w, QpB, qb0.w); }
        if (w < 2) { QpA = fmaf(pwa.z, QpA, qa0.z); QpB = fmaf(pwa.z, QpB, qb0.z); }
        if (w < 1) { QpA = fmaf(pwa.y, QpA, qa0.y); QpB = fmaf(pwa.y, QpB, qb0.y); }

        const float x0A = sx01[0][0], xn1A = sx01[0][1];
        const float x0B = sx01[1][0], xn1B = sx01[1][1];
        const float seedA = fmaf(cN, xn1A, -sN * x0A);  // prev_{N-1}
        const float seedB = fmaf(cN, xn1B, -sN * x0B);
        if (t == 0) {
            xa[0] = fmaf(sN, xn1A, cN * x0A);           // X_0 fix before replay
            xb[0] = fmaf(sN, xn1B, cN * x0B);
        }
        float prevA = fmaf(Pf, seedA, fmaf(Pe, QpA, QeA));
        float prevB = fmaf(Pf, seedB, fmaf(Pe, QpB, QeB));

        // Replay in place (coeffs reloaded from smem); ends with prev = prev_lo.
        {
            float4 C0 = sC0[t], C1 = sC1[t], S0 = sS0[t], S1 = sS1[t];
            const float cc[E] = {C0.x, C0.y, C0.z, C0.w, C1.x, C1.y, C1.z, C1.w};
            const float ss[E] = {S0.x, S0.y, S0.z, S0.w, S1.x, S1.y, S1.z, S1.w};
#pragma unroll
            for (int m = E - 1; m >= 0; --m) {
                if (lo + m == NN - 1) { xa[m] = 0.f; xb[m] = 0.f; continue; }
                const float xmA = xa[m], xmB = xb[m];
                xa[m] = fmaf(ss[m], xmA, cc[m] * prevA);
                prevA = fmaf(-ss[m], prevA, cc[m] * xmA);
                xb[m] = fmaf(ss[m], xmB, cc[m] * prevB);
                prevB = fmaf(-ss[m], prevB, cc[m] * xmB);
            }
        }

        float carryA = __shfl_up_sync(0xffffffffu, xa[E - 1], 1);
        float carryB = __shfl_up_sync(0xffffffffu, xb[E - 1], 1);
        if (t == 0) {
            carryA = prevA; carryB = prevB;
        } else if (warp_head) {
            carryA = fmaf(sprev, sxe[0][w - 1], cprev * prevA);
            carryB = fmaf(sprev, sxe[1][w - 1], cprev * prevB);
        }

        float* yrA = y + base * NN;
        float4 oa0, oa1;
        oa0.x = carryA; oa0.y = xa[0]; oa0.z = xa[1]; oa0.w = xa[2];
        oa1.x = xa[3];  oa1.y = xa[4]; oa1.z = xa[5]; oa1.w = xa[6];
        __stcs(reinterpret_cast<float4*>(yrA + lo), oa0);
        __stcs(reinterpret_cast<float4*>(yrA + lo) + 1, oa1);
        if (hasB) {
            float* yrB = yrA + NN;
            float4 ob0, ob1;
            ob0.x = carryB; ob0.y = xb[0]; ob0.z = xb[1]; ob0.w = xb[2];
            ob1.x = xb[3];  ob1.y = xb[4]; ob1.z = xb[5]; ob1.w = xb[6];
            __stcs(reinterpret_cast<float4*>(yrB + lo), ob0);
            __stcs(reinterpret_cast<float4*>(yrB + lo) + 1, ob1);
        }
    }

    // ======================= PHASE 2: rows C, D =======================
    {
        float xa[E], xb[E];
        xa[0] = cv0.x; xa[1] = cv0.y; xa[2] = cv0.z; xa[3] = cv0.w;
        xa[4] = cv1.x; xa[5] = cv1.y; xa[6] = cv1.z; xa[7] = cv1.w;
        xb[0] = dv0.x; xb[1] = dv0.y; xb[2] = dv0.z; xb[3] = dv0.w;
        xb[4] = dv1.x; xb[5] = dv1.y; xb[6] = dv1.z; xb[7] = dv1.w;

        float QA = 0.f, QB = 0.f;
        {
            float4 C0 = sC0[t], C1 = sC1[t], S0 = sS0[t], S1 = sS1[t];
            const float cc[E] = {C0.x, C0.y, C0.z, C0.w, C1.x, C1.y, C1.z, C1.w};
            const float ss[E] = {S0.x, S0.y, S0.z, S0.w, S1.x, S1.y, S1.z, S1.w};
#pragma unroll
            for (int m = E - 1; m >= 0; --m) {
                if (lo + m == NN - 1) continue;
                QA = fmaf(-ss[m], QA, cc[m] * xa[m]);
                QB = fmaf(-ss[m], QB, cc[m] * xb[m]);
            }
        }

#pragma unroll
        for (int di = 0, d = 1; di < 5; ++di, d <<= 1) {
            const float Wd = sW[t][di];
            float qa2 = __shfl_down_sync(0xffffffffu, QA, d);
            float qb2 = __shfl_down_sync(0xffffffffu, QB, d);
            QA = fmaf(Wd, qa2, QA);
            QB = fmaf(Wd, qb2, QB);
        }
        float QeA = __shfl_down_sync(0xffffffffu, QA, 1);
        float QeB = __shfl_down_sync(0xffffffffu, QB, 1);
        if (lid == 31) { QeA = 0.f; QeB = 0.f; }

        if (lid == 0) { wtQ[1][0][w] = QA; wtQ[1][1][w] = QB; }
        __syncthreads();                               // barrier 2

        float4 qa0 = *reinterpret_cast<const float4*>(&wtQ[1][0][0]);
        float4 qa1 = *reinterpret_cast<const float4*>(&wtQ[1][0][4]);
        float4 qb0 = *reinterpret_cast<const float4*>(&wtQ[1][1][0]);
        float4 qb1 = *reinterpret_cast<const float4*>(&wtQ[1][1][4]);
        float4 pwa = *reinterpret_cast<const float4*>(&spw[0]);
        float4 pwb = *reinterpret_cast<const float4*>(&spw[4]);
        float QpA = 0.f, QpB = 0.f;
        if (w < 7) { QpA = qa1.w;                   QpB = qb1.w; }
        if (w < 6) { QpA = fmaf(pwb.z, QpA, qa1.z); QpB = fmaf(pwb.z, QpB, qb1.z); }
        if (w < 5) { QpA = fmaf(pwb.y, QpA, qa1.y); QpB = fmaf(pwb.y, QpB, qb1.y); }
        if (w < 4) { QpA = fmaf(pwb.x, QpA, qa1.x); QpB = fmaf(pwb.x, QpB, qb1.x); }
        if (w < 3) { QpA = fmaf(pwa.w, QpA, qa0.w); QpB = fmaf(pwa.w, QpB, qb0.w); }
        if (w < 2) { QpA = fmaf(pwa.z, QpA, qa0.z); QpB = fmaf(pwa.z, QpB, qb0.z); }
        if (w < 1) { QpA = fmaf(pwa.y, QpA, qa0.y); QpB = fmaf(pwa.y, QpB, qb0.y); }

        const float x0A = sx01[2][0], xn1A = sx01[2][1];
        const float x0B = sx01[3][0], xn1B = sx01[3][1];
        const float seedA = fmaf(cN, xn1A, -sN * x0A);
        const float seedB = fmaf(cN, xn1B, -sN * x0B);
        if (t == 0) {
            xa[0] = fmaf(sN, xn1A, cN * x0A);
            xb[0] = fmaf(sN, xn1B, cN * x0B);
        }
        float prevA = fmaf(Pf, seedA, fmaf(Pe, QpA, QeA));
        float prevB = fmaf(Pf, seedB, fmaf(Pe, QpB, QeB));

        {
            float4 C0 = sC0[t], C1 = sC1[t], S0 = sS0[t], S1 = sS1[t];
            const float cc[E] = {C0.x, C0.y, C0.z, C0.w, C1.x, C1.y, C1.z, C1.w};
            const float ss[E] = {S0.x, S0.y, S0.z, S0.w, S1.x, S1.y, S1.z, S1.w};
#pragma unroll
            for (int m = E - 1; m >= 0; --m) {
                if (lo + m == NN - 1) { xa[m] = 0.f; xb[m] = 0.f; continue; }
                const float xmA = xa[m], xmB = xb[m];
                xa[m] = fmaf(ss[m], xmA, cc[m] * prevA);
                prevA = fmaf(-ss[m], prevA, cc[m] * xmA);
                xb[m] = fmaf(ss[m], xmB, cc[m] * prevB);
                prevB = fmaf(-ss[m], prevB, cc[m] * xmB);
            }
        }

        float carryA = __shfl_up_sync(0xffffffffu, xa[E - 1], 1);
        float carryB = __shfl_up_sync(0xffffffffu, xb[E - 1], 1);
        if (t == 0) {
            carryA = prevA; carryB = prevB;
        } else if (warp_head) {
            carryA = fmaf(sprev, sxe[2][w - 1], cprev * prevA);
            carryB = fmaf(sprev, sxe[3][w - 1], cprev * prevB);
        }

        if (hasC) {
            float* yrC = y + (base + 2) * NN;
            float4 oc0, oc1;
            oc0.x = carryA; oc0.y = xa[0]; oc0.z = xa[1]; oc0.w = xa[2];
            oc1.x = xa[3];  oc1.y = xa[4]; oc1.z = xa[5]; oc1.w = xa[6];
            __stcs(reinterpret_cast<float4*>(yrC + lo), oc0);
            __stcs(reinterpret_cast<float4*>(yrC + lo) + 1, oc1);
        }
        if (hasD) {
            float* yrD = y + (base + 3) * NN;
            float4 od0, od1;
            od0.x = carryB; od0.y = xb[0]; od0.z = xb[1]; od0.w = xb[2];
            od1.x = xb[3];  od1.y = xb[4]; od1.z = xb[5]; od1.w = xb[6];
            __stcs(reinterpret_cast<float4*>(yrD + lo), od0);
            __stcs(reinterpret_cast<float4*>(yrD + lo) + 1, od1);
        }
    }
}

extern "C" void kernel_launch(void* const* d_in, const int* in_sizes, int n_in,
                              void* d_out, int out_size) {
    const float* x   = (const float*)d_in[0];   // (B, N) fp32
    const float* ang = (const float*)d_in[1];   // (N,)  fp32
    float* y = (float*)d_out;                   // (B, N) fp32

    const int rows   = out_size / NN;           // B = 16384
    const int blocks = (rows + R - 1) / R;      // 4096
    givens_kernel<<<blocks, T>>>(x, ang, y, rows);
}

// round 15
// speedup vs baseline: 1.0825x; 1.0413x over previous
#include <cuda_runtime.h>
#include <cstdint>

// Problem constants: x is (16384, 2048) fp32, angles (2048,) fp32, out (16384, 2048) fp32.
constexpr int NN = 2048;   // row length n
constexpr int T  = 256;    // threads per block
constexpr int E  = 8;      // elements per thread (T*E == NN)
constexpr int R  = 4;      // rows per block, straight-line quad-load / dual-compute

// y_row = G_0 (G_1 (... (G_{N-1} x_row))). First-order affine recurrence on the
// carry; Q-only weighted warp suffix scan; inline prep. ALL FOUR rows' loads
// issue up front (DRAM latency overlaps prep); rows C/D are parked in smem
// (thread-private slices, conflict-free) to keep register peak at the
// 64-reg / 4-CTA budget, and coefficients stay in registers (no per-phase LDS).
__global__ void __launch_bounds__(T, 4) givens_kernel(const float* __restrict__ x,
                                                      const float* __restrict__ ang,
                                                      float* __restrict__ y,
                                                      int rows) {
    __shared__ __align__(16) float4 stg[4][T];    // staged rows C,D: cv0,cv1,dv0,dv1
    __shared__ __align__(16) float spw[8];        // per-warp P totals
    __shared__ float scs[8][2];                   // per-warp tail coeffs (c,s at lo+7, lane 31)
    __shared__ float stail[2];                    // cN, sN
    __shared__ __align__(16) float wtQ[2][2][8];  // [phase][row-in-pair][warp]
    __shared__ float sxe[2][8];                   // lane-31 x[lo+7] per warp (rows A,B)
    __shared__ float sx01[2][2];                  // x[0], x[N-1] (rows A,B)

    const int t   = threadIdx.x;
    const int lid = t & 31;
    const int w   = t >> 5;
    const int lo  = t * E;
    const long base = (long)blockIdx.x * R;
    if (base >= rows) return;

    const bool hasB = base + 1 < rows;
    const bool hasC = base + 2 < rows;
    const bool hasD = base + 3 < rows;
    const float* xrA = x + base * NN;
    const float* xrB = xrA + (hasB ? NN : 0);
    const float* xrC = xrA + (hasC ? 2 * NN : 0);
    const float* xrD = xrA + (hasD ? 3 * NN : 0);

    // ================= 1. issue ALL row loads first =================
    float4 a0 = __ldcs(reinterpret_cast<const float4*>(xrA + lo));
    float4 a1 = __ldcs(reinterpret_cast<const float4*>(xrA + lo) + 1);
    float4 b0 = __ldcs(reinterpret_cast<const float4*>(xrB + lo));
    float4 b1 = __ldcs(reinterpret_cast<const float4*>(xrB + lo) + 1);
    float4 cv0 = __ldcs(reinterpret_cast<const float4*>(xrC + lo));
    float4 cv1 = __ldcs(reinterpret_cast<const float4*>(xrC + lo) + 1);
    float4 dv0 = __ldcs(reinterpret_cast<const float4*>(xrD + lo));
    float4 dv1 = __ldcs(reinterpret_cast<const float4*>(xrD + lo) + 1);

    // ================= 2. inline prep in registers (overlaps DRAM) =================
    float cc[E], ss[E];
    {
        float4 g0 = reinterpret_cast<const float4*>(ang + lo)[0];
        float4 g1 = reinterpret_cast<const float4*>(ang + lo)[1];
        __sincosf(g0.x, &ss[0], &cc[0]);
        __sincosf(g0.y, &ss[1], &cc[1]);
        __sincosf(g0.z, &ss[2], &cc[2]);
        __sincosf(g0.w, &ss[3], &cc[3]);
        __sincosf(g1.x, &ss[4], &cc[4]);
        __sincosf(g1.y, &ss[5], &cc[5]);
        __sincosf(g1.z, &ss[6], &cc[6]);
        __sincosf(g1.w, &ss[7], &cc[7]);
    }

    // Per-thread P = prod of (-s_k) over this chunk (k = N-1 is the seed, skipped).
    float P = 1.f;
#pragma unroll
    for (int m = E - 1; m >= 0; --m) {
        if (lo + m == NN - 1) continue;
        P *= -ss[m];
    }

    // Warp suffix-scan jump weights by shuffle product-doubling (0 past warp end).
    float W[5];
    {
        float S = P;
        W[0] = (lid + 1 < 32) ? S : 0.f;
#pragma unroll
        for (int di = 1; di < 5; ++di) {
            const int h = 1 << (di - 1);
            float Sn = __shfl_down_sync(0xffffffffu, S, h);
            S *= (lid + h < 32) ? Sn : 0.f;
            W[di] = (lid + (1 << di) < 32) ? S : 0.f;
        }
    }

    // Warp inclusive suffix scan of P -> Pe (exclusive), warp totals.
    float Pe;
    {
        float Pscan = P;
#pragma unroll
        for (int d = 1; d < 32; d <<= 1) {
            float tmp = __shfl_down_sync(0xffffffffu, Pscan, d);
            if (lid + d < 32) Pscan *= tmp;
        }
        Pe = __shfl_down_sync(0xffffffffu, Pscan, 1);
        if (lid == 31) Pe = 1.f;
        if (lid == 0)   spw[w] = Pscan;
        if (lid == 31)  { scs[w][0] = cc[7]; scs[w][1] = ss[7]; }
        if (t == T - 1) { stail[0] = cc[7]; stail[1] = ss[7]; }
    }
    __syncthreads();                               // barrier 0: prep tables ONLY (no DRAM wait)

    float Pf = Pe;
    for (int w2 = w + 1; w2 < 8; ++w2) Pf *= spw[w2];   // block-exclusive product
    const float cN = stail[0];
    const float sN = stail[1];
    const bool warp_head = (lid == 0) && (w > 0);
    float cprev = 0.f, sprev = 0.f;
    if (warp_head) { cprev = scs[w - 1][0]; sprev = scs[w - 1][1]; }

    // ---- park rows C/D in smem (frees 16 regs before phase-1 compute) ----
    stg[0][t] = cv0;
    stg[1][t] = cv1;
    stg[2][t] = dv0;
    stg[3][t] = dv1;

    // ======================= PHASE 1: rows A, B =======================
    {
        float xa[E], xb[E];
        xa[0] = a0.x; xa[1] = a0.y; xa[2] = a0.z; xa[3] = a0.w;
        xa[4] = a1.x; xa[5] = a1.y; xa[6] = a1.z; xa[7] = a1.w;
        xb[0] = b0.x; xb[1] = b0.y; xb[2] = b0.z; xb[3] = b0.w;
        xb[4] = b1.x; xb[5] = b1.y; xb[6] = b1.z; xb[7] = b1.w;

        // Boundary exchange (visible at barrier 1; consumed after it).
        if (lid == 31) { sxe[0][w] = xa[7]; sxe[1][w] = xb[7]; }
        if (t == 0)    { sx01[0][0] = xa[0]; sx01[1][0] = xb[0]; }
        if (t == T-1)  { sx01[0][1] = xa[7]; sx01[1][1] = xb[7]; }

        // Q composition (thread 0's Q is consumed by nobody; uncorrected x[0] OK).
        float QA = 0.f, QB = 0.f;
#pragma unroll
        for (int m = E - 1; m >= 0; --m) {
            if (lo + m == NN - 1) continue;        // seed step
            QA = fmaf(-ss[m], QA, cc[m] * xa[m]);
            QB = fmaf(-ss[m], QB, cc[m] * xb[m]);
        }

        // Q-only weighted warp suffix scan, rows interleaved.
#pragma unroll
        for (int di = 0, d = 1; di < 5; ++di, d <<= 1) {
            float qa2 = __shfl_down_sync(0xffffffffu, QA, d);
            float qb2 = __shfl_down_sync(0xffffffffu, QB, d);
            QA = fmaf(W[di], qa2, QA);
            QB = fmaf(W[di], qb2, QB);
        }
        float QeA = __shfl_down_sync(0xffffffffu, QA, 1);
        float QeB = __shfl_down_sync(0xffffffffu, QB, 1);
        if (lid == 31) { QeA = 0.f; QeB = 0.f; }

        if (lid == 0) { wtQ[0][0][w] = QA; wtQ[0][1][w] = QB; }
        __syncthreads();                           // barrier 1: wtQ + stage + boundaries

        // Cross-warp Horner over later warps (pw via short-lived LDS.128).
        float4 qa0 = *reinterpret_cast<const float4*>(&wtQ[0][0][0]);
        float4 qa1 = *reinterpret_cast<const float4*>(&wtQ[0][0][4]);
        float4 qb0 = *reinterpret_cast<const float4*>(&wtQ[0][1][0]);
        float4 qb1 = *reinterpret_cast<const float4*>(&wtQ[0][1][4]);
        float4 pwa = *reinterpret_cast<const float4*>(&spw[0]);
        float4 pwb = *reinterpret_cast<const float4*>(&spw[4]);
        float QpA = 0.f, QpB = 0.f;
        if (w < 7) { QpA = qa1.w;                   QpB = qb1.w; }
        if (w < 6) { QpA = fmaf(pwb.z, QpA, qa1.z); QpB = fmaf(pwb.z, QpB, qb1.z); }
        if (w < 5) { QpA = fmaf(pwb.y, QpA, qa1.y); QpB = fmaf(pwb.y, QpB, qb1.y); }
        if (w < 4) { QpA = fmaf(pwb.x, QpA, qa1.x); QpB = fmaf(pwb.x, QpB, qb1.x); }
        if (w < 3) { QpA = fmaf(pwa.w, QpA, qa0.w); QpB = fmaf(pwa.w, QpB, qb0.w); }
        if (w < 2) { QpA = fmaf(pwa.z, QpA, qa0.z); QpB = fmaf(pwa.z, QpB, qb0.z); }
        if (w < 1) { QpA = fmaf(pwa.y, QpA, qa0.y); QpB = fmaf(pwa.y, QpB, qb0.y); }

        const float x0A = sx01[0][0], xn1A = sx01[0][1];
        const float x0B = sx01[1][0], xn1B = sx01[1][1];
        const float seedA = fmaf(cN, xn1A, -sN * x0A);  // prev_{N-1}
        const float seedB = fmaf(cN, xn1B, -sN * x0B);
        if (t == 0) {
            xa[0] = fmaf(sN, xn1A, cN * x0A);           // X_0 fix before replay
            xb[0] = fmaf(sN, xn1B, cN * x0B);
        }
        float prevA = fmaf(Pf, seedA, fmaf(Pe, QpA, QeA));
        float prevB = fmaf(Pf, seedB, fmaf(Pe, QpB, QeB));

        // Replay in place; ends with prev = prev_lo.
#pragma unroll
        for (int m = E - 1; m >= 0; --m) {
            if (lo + m == NN - 1) { xa[m] = 0.f; xb[m] = 0.f; continue; }
            const float xmA = xa[m], xmB = xb[m];
            xa[m] = fmaf(ss[m], xmA, cc[m] * prevA);
            prevA = fmaf(-ss[m], prevA, cc[m] * xmA);
            xb[m] = fmaf(ss[m], xmB, cc[m] * prevB);
            prevB = fmaf(-ss[m], prevB, cc[m] * xmB);
        }

        float carryA = __shfl_up_sync(0xffffffffu, xa[E - 1], 1);
        float carryB = __shfl_up_sync(0xffffffffu, xb[E - 1], 1);
        if (t == 0) {
            carryA = prevA; carryB = prevB;
        } else if (warp_head) {
            carryA = fmaf(sprev, sxe[0][w - 1], cprev * prevA);
            carryB = fmaf(sprev, sxe[1][w - 1], cprev * prevB);
        }

        float* yrA = y + base * NN;
        float4 oa0, oa1;
        oa0.x = carryA; oa0.y = xa[0]; oa0.z = xa[1]; oa0.w = xa[2];
        oa1.x = xa[3];  oa1.y = xa[4]; oa1.z = xa[5]; oa1.w = xa[6];
        __stcs(reinterpret_cast<float4*>(yrA + lo), oa0);
        __stcs(reinterpret_cast<float4*>(yrA + lo) + 1, oa1);
        if (hasB) {
            float* yrB = yrA + NN;
            float4 ob0, ob1;
            ob0.x = carryB; ob0.y = xb[0]; ob0.z = xb[1]; ob0.w = xb[2];
            ob1.x = xb[3];  ob1.y = xb[4]; ob1.z = xb[5]; ob1.w = xb[6];
            __stcs(reinterpret_cast<float4*>(yrB + lo), ob0);
            __stcs(reinterpret_cast<float4*>(yrB + lo) + 1, ob1);
        }
    }

    // ======================= PHASE 2: rows C, D (from the staged tile) =======================
    {
        float xa[E], xb[E];
        {
            float4 c0 = stg[0][t], c1 = stg[1][t];
            float4 d0 = stg[2][t], d1 = stg[3][t];
            xa[0] = c0.x; xa[1] = c0.y; xa[2] = c0.z; xa[3] = c0.w;
            xa[4] = c1.x; xa[5] = c1.y; xa[6] = c1.z; xa[7] = c1.w;
            xb[0] = d0.x; xb[1] = d0.y; xb[2] = d0.z; xb[3] = d0.w;
            xb[4] = d1.x; xb[5] = d1.y; xb[6] = d1.z; xb[7] = d1.w;
        }
        // Boundary values straight from the staged tile (no exchange needed).
        const float x0C = stg[0][0].x,     xn1C = stg[1][T - 1].w;
        const float x0D = stg[2][0].x,     xn1D = stg[3][T - 1].w;
        const float xpvC = warp_head ? stg[1][t - 1].w : 0.f;
        const float xpvD = warp_head ? stg[3][t - 1].w : 0.f;

        const float seedC = fmaf(cN, xn1C, -sN * x0C);
        const float seedD = fmaf(cN, xn1D, -sN * x0D);
        if (t == 0) {
            xa[0] = fmaf(sN, xn1C, cN * x0C);
            xb[0] = fmaf(sN, xn1D, cN * x0D);
        }

        float QA = 0.f, QB = 0.f;
#pragma unroll
        for (int m = E - 1; m >= 0; --m) {
            if (lo + m == NN - 1) continue;
            QA = fmaf(-ss[m], QA, cc[m] * xa[m]);
            QB = fmaf(-ss[m], QB, cc[m] * xb[m]);
        }

#pragma unroll
        for (int di = 0, d = 1; di < 5; ++di, d <<= 1) {
            float qa2 = __shfl_down_sync(0xffffffffu, QA, d);
            float qb2 = __shfl_down_sync(0xffffffffu, QB, d);
            QA = fmaf(W[di], qa2, QA);
            QB = fmaf(W[di], qb2, QB);
        }
        float QeA = __shfl_down_sync(0xffffffffu, QA, 1);
        float QeB = __shfl_down_sync(0xffffffffu, QB, 1);
        if (lid == 31) { QeA = 0.f; QeB = 0.f; }

        if (lid == 0) { wtQ[1][0][w] = QA; wtQ[1][1][w] = QB; }
        __syncthreads();                           // barrier 2

        float4 qa0 = *reinterpret_cast<const float4*>(&wtQ[1][0][0]);
        float4 qa1 = *reinterpret_cast<const float4*>(&wtQ[1][0][4]);
        float4 qb0 = *reinterpret_cast<const float4*>(&wtQ[1][1][0]);
        float4 qb1 = *reinterpret_cast<const float4*>(&wtQ[1][1][4]);
        float4 pwa = *reinterpret_cast<const float4*>(&spw[0]);
        float4 pwb = *reinterpret_cast<const float4*>(&spw[4]);
        float QpA = 0.f, QpB = 0.f;
        if (w < 7) { QpA = qa1.w;                   QpB = qb1.w; }
        if (w < 6) { QpA = fmaf(pwb.z, QpA, qa1.z); QpB = fmaf(pwb.z, QpB, qb1.z); }
        if (w < 5) { QpA = fmaf(pwb.y, QpA, qa1.y); QpB = fmaf(pwb.y, QpB, qb1.y); }
        if (w < 4) { QpA = fmaf(pwb.x, QpA, qa1.x); QpB = fmaf(pwb.x, QpB, qb1.x); }
        if (w < 3) { QpA = fmaf(pwa.w, QpA, qa0.w); QpB = fmaf(pwa.w, QpB, qb0.w); }
        if (w < 2) { QpA = fmaf(pwa.z, QpA, qa0.z); QpB = fmaf(pwa.z, QpB, qb0.z); }
        if (w < 1) { QpA = fmaf(pwa.y, QpA, qa0.y); QpB = fmaf(pwa.y, QpB, qb0.y); }

        float prevA = fmaf(Pf, seedC, fmaf(Pe, QpA, QeA));
        float prevB = fmaf(Pf, seedD, fmaf(Pe, QpB, QeB));

#pragma unroll
        for (int m = E - 1; m >= 0; --m) {
            if (lo + m == NN - 1) { xa[m] = 0.f; xb[m] = 0.f; continue; }
            const float xmA = xa[m], xmB = xb[m];
            xa[m] = fmaf(ss[m], xmA, cc[m] * prevA);
            prevA = fmaf(-ss[m], prevA, cc[m] * xmA);
            xb[m] = fmaf(ss[m], xmB, cc[m] * prevB);
            prevB = fmaf(-ss[m], prevB, cc[m] * xmB);
        }

        float carryA = __shfl_up_sync(0xffffffffu, xa[E - 1], 1);
        float carryB = __shfl_up_sync(0xffffffffu, xb[E - 1], 1);
        if (t == 0) {
            carryA = prevA; carryB = prevB;
        } else if (warp_head) {
            carryA = fmaf(sprev, xpvC, cprev * prevA);
            carryB = fmaf(sprev, xpvD, cprev * prevB);
        }

        if (hasC) {
            float* yrC = y + (base + 2) * NN;
            float4 oc0, oc1;
            oc0.x = carryA; oc0.y = xa[0]; oc0.z = xa[1]; oc0.w = xa[2];
            oc1.x = xa[3];  oc1.y = xa[4]; oc1.z = xa[5]; oc1.w = xa[6];
            __stcs(reinterpret_cast<float4*>(yrC + lo), oc0);
            __stcs(reinterpret_cast<float4*>(yrC + lo) + 1, oc1);
        }
        if (hasD) {
            float* yrD = y + (base + 3) * NN;
            float4 od0, od1;
            od0.x = carryB; od0.y = xb[0]; od0.z = xb[1]; od0.w = xb[2];
            od1.x = xb[3];  od1.y = xb[4]; od1.z = xb[5]; od1.w = xb[6];
            __stcs(reinterpret_cast<float4*>(yrD + lo), od0);
            __stcs(reinterpret_cast<float4*>(yrD + lo) + 1, od1);
        }
    }
}

extern "C" void kernel_launch(void* const* d_in, const int* in_sizes, int n_in,
                              void* d_out, int out_size) {
    const float* x   = (const float*)d_in[0];   // (B, N) fp32
    const float* ang = (const float*)d_in[1];   // (N,)  fp32
    float* y = (float*)d_out;                   // (B, N) fp32

    const int rows   = out_size / NN;           // B = 16384
    const int blocks = (rows + R - 1) / R;      // 4096
    givens_kernel<<<blocks, T>>>(x, ang, y, rows);
}